// round 7
// baseline (speedup 1.0000x reference)
#include <cuda_runtime.h>
#include <cuda_fp16.h>

#define NS   8
#define HH   128
#define WW   128
#define HWP  (HH*WW)      // 16384
#define BB   32
#define EPSV 1e-8f
#define TH   8            // rows per block in half-step kernel

// ---------------- scratch (static device memory, no allocation) ----------------
// Total loop working set = 67 + 4*8.4 = 100.6 MB  ->  L2-resident (126 MB)
__device__ __half g_H0[(size_t)BB*NS*NS*HWP];   // 67 MB   [b][i][j][h][w]
__device__ __half g_r [(size_t)BB*NS*HWP];      // 8.4 MB  [b][i][h][w]
__device__ __half g_c [(size_t)BB*NS*HWP];      // 8.4 MB  [b][j][h][w]
__device__ __half g_mA[(size_t)BB*NS*HWP];      // 8.4 MB marginal ping
__device__ __half g_mB[(size_t)BB*NS*HWP];      // 8.4 MB marginal pong

// ---------------- separable gaussian weights (bandwidth 0.5, normalized) -------
constexpr double d_e2 = 0.13533528323661270231;
constexpr double d_e8 = 0.00033546262790251185;
constexpr double d_s  = 1.0 + 2.0*d_e2 + 2.0*d_e8;
#define KW0 ((float)(d_e8/d_s))
#define KW1 ((float)(d_e2/d_s))
#define KW2 ((float)(1.0 /d_s))

// ================= init: H0 = exp(log), marg0 = sum_j H0, r=c=1 ================
__global__ void k_init(const float* __restrict__ lg) {
    int t   = blockIdx.x*blockDim.x + threadIdx.x;   // 131072 threads
    int b   = t >> 12;                                // 4096 thread-groups / batch
    int pix = (t & 4095) << 2;                        // 4 consecutive w pixels

    const __half2 one2 = __floats2half2_rn(1.f, 1.f);
    #pragma unroll
    for (int i = 0; i < NS; i++) {
        float a0 = 0.f, a1 = 0.f, a2 = 0.f, a3 = 0.f;
        #pragma unroll
        for (int j = 0; j < NS; j++) {
            size_t off = ((size_t)(b*NS*NS + i*NS + j))*HWP + pix;
            float4 v = *(const float4*)(lg + off);
            float e0 = expf(v.x), e1 = expf(v.y), e2 = expf(v.z), e3 = expf(v.w);
            __half2* hp = (__half2*)(g_H0 + off);
            hp[0] = __floats2half2_rn(e0, e1);
            hp[1] = __floats2half2_rn(e2, e3);
            a0 += e0; a1 += e1; a2 += e2; a3 += e3;
        }
        size_t moff = ((size_t)(b*NS + i))*HWP + pix;
        __half2* mp = (__half2*)(g_mA + moff);
        mp[0] = __floats2half2_rn(a0, a1);
        mp[1] = __floats2half2_rn(a2, a3);
        ((__half2*)(g_r + moff))[0] = one2;
        ((__half2*)(g_r + moff))[1] = one2;
        ((__half2*)(g_c + moff))[0] = one2;
        ((__half2*)(g_c + moff))[1] = one2;
    }
}

// ================= fused half step ==============================================
// MODE 0: smooth marg_in -> r /= (s+eps); marg_out_j = c_j * sum_i H0[i][j]*r_i
// MODE 1: smooth marg_in -> c /= (s+eps); marg_out_i = r_i * sum_j H0[i][j]*c_j
template<int MODE>
__global__ __launch_bounds__(256, 2) void k_half(int ping) {
    __shared__ __align__(16) __half sm_m[TH+4][NS][WW];  // marginal tile + halo (24 KB)

    const __half* __restrict__ min_ = ping ? g_mB : g_mA;
    __half*       __restrict__ mout = ping ? g_mA : g_mB;
    __half*       upd = (MODE == 0) ? g_r : g_c;
    const __half* oth = (MODE == 0) ? g_c : g_r;

    const int b    = blockIdx.y;
    const int h0   = blockIdx.x * TH;
    const int lane = threadIdx.x;              // 32 lanes = one full row (4 px each)
    const int tid  = threadIdx.y * 32 + lane;

    const int h  = h0 + threadIdx.y;
    const int w0 = lane << 2;
    const size_t pixoff = (size_t)h*WW + w0;
    const size_t hbase  = (size_t)b*NS*NS*HWP + pixoff;

    // ---- load marginal tile (rows h0-2 .. h0+TH+1, circular) -------------------
    for (int idx = tid; idx < (TH+4)*NS*(WW/8); idx += 256) {
        int rr  = idx >> 7;                     // / (8*16)
        int rem = idx & 127;
        int ch  = rem >> 4;
        int w8  = (rem & 15) << 3;
        int gh  = (h0 - 2 + rr) & (HH-1);
        *(uint4*)(&sm_m[rr][ch][w8]) =
            *(const uint4*)(min_ + ((size_t)(b*NS + ch))*HWP + gh*WW + w8);
    }
    __syncthreads();

    const int lmL = (lane + 31) & 31, lmR = (lane + 1) & 31;

    // ---- smoothing (vertical: smem taps, horizontal: warp shuffle) + update ----
    float un[NS][4];
    #pragma unroll
    for (int u = 0; u < NS; u++) {
        // vertical 5-tap on this thread's 4 pixels
        float4 vr;
        {
            uint2 q0 = *(const uint2*)(&sm_m[threadIdx.y    ][u][w0]);
            uint2 q1 = *(const uint2*)(&sm_m[threadIdx.y + 1][u][w0]);
            uint2 q2 = *(const uint2*)(&sm_m[threadIdx.y + 2][u][w0]);
            uint2 q3 = *(const uint2*)(&sm_m[threadIdx.y + 3][u][w0]);
            uint2 q4 = *(const uint2*)(&sm_m[threadIdx.y + 4][u][w0]);
            float2 a0 = __half22float2(*(__half2*)&q0.x), b0_ = __half22float2(*(__half2*)&q0.y);
            float2 a1 = __half22float2(*(__half2*)&q1.x), b1_ = __half22float2(*(__half2*)&q1.y);
            float2 a2 = __half22float2(*(__half2*)&q2.x), b2_ = __half22float2(*(__half2*)&q2.y);
            float2 a3 = __half22float2(*(__half2*)&q3.x), b3_ = __half22float2(*(__half2*)&q3.y);
            float2 a4 = __half22float2(*(__half2*)&q4.x), b4_ = __half22float2(*(__half2*)&q4.y);
            vr.x = KW0*a0.x + KW1*a1.x + KW2*a2.x + KW1*a3.x + KW0*a4.x;
            vr.y = KW0*a0.y + KW1*a1.y + KW2*a2.y + KW1*a3.y + KW0*a4.y;
            vr.z = KW0*b0_.x + KW1*b1_.x + KW2*b2_.x + KW1*b3_.x + KW0*b4_.x;
            vr.w = KW0*b0_.y + KW1*b1_.y + KW2*b2_.y + KW1*b3_.y + KW0*b4_.y;
        }
        // horizontal 5-tap with circular wrap via warp shuffle (warp = full row)
        float lz = __shfl_sync(0xffffffffu, vr.z, lmL);   // pixel w0-2
        float lw = __shfl_sync(0xffffffffu, vr.w, lmL);   // pixel w0-1
        float rx = __shfl_sync(0xffffffffu, vr.x, lmR);   // pixel w0+4
        float ry = __shfl_sync(0xffffffffu, vr.y, lmR);   // pixel w0+5
        float s0 = KW0*lz   + KW1*lw   + KW2*vr.x + KW1*vr.y + KW0*vr.z;
        float s1 = KW0*lw   + KW1*vr.x + KW2*vr.y + KW1*vr.z + KW0*vr.w;
        float s2 = KW0*vr.x + KW1*vr.y + KW2*vr.z + KW1*vr.w + KW0*rx;
        float s3 = KW0*vr.y + KW1*vr.z + KW2*vr.w + KW1*rx   + KW0*ry;

        size_t off = ((size_t)(b*NS + u))*HWP + pixoff;
        uint2 fr = *(const uint2*)(upd + off);
        float2 f01 = __half22float2(*(__half2*)&fr.x);
        float2 f23 = __half22float2(*(__half2*)&fr.y);
        un[u][0] = __fdividef(f01.x, s0 + EPSV);
        un[u][1] = __fdividef(f01.y, s1 + EPSV);
        un[u][2] = __fdividef(f23.x, s2 + EPSV);
        un[u][3] = __fdividef(f23.y, s3 + EPSV);
        __half2* up = (__half2*)(upd + off);
        up[0] = __floats2half2_rn(un[u][0], un[u][1]);
        up[1] = __floats2half2_rn(un[u][2], un[u][3]);
    }

    // ---- 8x8 contraction, split into two v-halves to cap live registers --------
    #pragma unroll
    for (int vh = 0; vh < 2; vh++) {
        float acc[4][4];
        #pragma unroll
        for (int v = 0; v < 4; v++)
            acc[v][0] = acc[v][1] = acc[v][2] = acc[v][3] = 0.f;

        #pragma unroll
        for (int u = 0; u < NS; u++) {
            #pragma unroll
            for (int v = 0; v < 4; v++) {
                int vv = vh*4 + v;
                int cc = (MODE == 0) ? (u*NS + vv) : (vv*NS + u);
                uint2 raw = *(const uint2*)(g_H0 + hbase + (size_t)cc*HWP);
                float2 f0 = __half22float2(*reinterpret_cast<__half2*>(&raw.x));
                float2 f1 = __half22float2(*reinterpret_cast<__half2*>(&raw.y));
                acc[v][0] += f0.x * un[u][0];
                acc[v][1] += f0.y * un[u][1];
                acc[v][2] += f1.x * un[u][2];
                acc[v][3] += f1.y * un[u][3];
            }
        }

        #pragma unroll
        for (int v = 0; v < 4; v++) {
            int vv = vh*4 + v;
            size_t off = ((size_t)(b*NS + vv))*HWP + pixoff;
            uint2 ov = *(const uint2*)(oth + off);
            float2 o01 = __half22float2(*(__half2*)&ov.x);
            float2 o23 = __half22float2(*(__half2*)&ov.y);
            __half2* mp = (__half2*)(mout + off);
            mp[0] = __floats2half2_rn(acc[v][0]*o01.x, acc[v][1]*o01.y);
            mp[1] = __floats2half2_rn(acc[v][2]*o23.x, acc[v][3]*o23.y);
        }
    }
}

// ================= final: out = exp(log)*r_i*c_j + eps (fp32 path) =============
__global__ void k_final(const float* __restrict__ lg, float* __restrict__ out) {
    int t   = blockIdx.x*blockDim.x + threadIdx.x;
    int b   = t >> 12;
    int pix = (t & 4095) << 2;

    float cf[NS][4];
    #pragma unroll
    for (int j = 0; j < NS; j++) {
        uint2 cv = *(const uint2*)(g_c + ((size_t)(b*NS + j))*HWP + pix);
        float2 c01 = __half22float2(*(__half2*)&cv.x);
        float2 c23 = __half22float2(*(__half2*)&cv.y);
        cf[j][0] = c01.x; cf[j][1] = c01.y; cf[j][2] = c23.x; cf[j][3] = c23.y;
    }
    #pragma unroll
    for (int i = 0; i < NS; i++) {
        uint2 rw = *(const uint2*)(g_r + ((size_t)(b*NS + i))*HWP + pix);
        float2 r01 = __half22float2(*(__half2*)&rw.x);
        float2 r23 = __half22float2(*(__half2*)&rw.y);
        #pragma unroll
        for (int j = 0; j < NS; j++) {
            size_t off = ((size_t)(b*NS*NS + i*NS + j))*HWP + pix;
            float4 v = *(const float4*)(lg + off);
            float4 o;
            o.x = expf(v.x)*r01.x*cf[j][0] + EPSV;
            o.y = expf(v.y)*r01.y*cf[j][1] + EPSV;
            o.z = expf(v.z)*r23.x*cf[j][2] + EPSV;
            o.w = expf(v.w)*r23.y*cf[j][3] + EPSV;
            *(float4*)(out + off) = o;
        }
    }
}

// ================= launch =======================================================
extern "C" void kernel_launch(void* const* d_in, const int* in_sizes, int n_in,
                              void* d_out, int out_size) {
    (void)in_sizes; (void)n_in; (void)out_size;
    const float* lg  = (const float*)d_in[0];
    float*       out = (float*)d_out;

    k_init<<<512, 256>>>(lg);

    dim3 hb(32, TH);                 // 256 threads: one warp per row
    dim3 hg(HH/TH, BB);              // (16, 32) = 512 blocks, ALL batches / launch
    for (int it = 0; it < 20; it++) {
        k_half<0><<<hg, hb>>>(0);    // row step: in=mA, out=mB, update r
        k_half<1><<<hg, hb>>>(1);    // col step: in=mB, out=mA, update c
    }

    k_final<<<512, 256>>>(lg, out);
}

// round 8
// speedup vs baseline: 1.2112x; 1.2112x over previous
#include <cuda_runtime.h>
#include <cuda_fp16.h>

#define NS   8
#define HH   128
#define WW   128
#define HWP  (HH*WW)      // 16384
#define BB   32
#define BSPL 16           // batches per temporal pass (L2 residency ~50 MB)
#define EPSV 1e-8f
#define TH   8            // rows per block in half-step kernel

// ---------------- scratch (static device memory, no allocation) ----------------
__device__ __half g_H0[(size_t)BB*NS*NS*HWP];   // 67 MB   [b][i][j][h][w]
__device__ __half g_r [(size_t)BB*NS*HWP];      // 8.4 MB  [b][i][h][w]
__device__ __half g_c [(size_t)BB*NS*HWP];      // 8.4 MB  [b][j][h][w]
__device__ __half g_mA[(size_t)BB*NS*HWP];      // 8.4 MB marginal ping
__device__ __half g_mB[(size_t)BB*NS*HWP];      // 8.4 MB marginal pong

// ---------------- separable gaussian weights (bandwidth 0.5, normalized) -------
constexpr double d_e2 = 0.13533528323661270231;
constexpr double d_e8 = 0.00033546262790251185;
constexpr double d_s  = 1.0 + 2.0*d_e2 + 2.0*d_e8;
#define KW0 ((float)(d_e8/d_s))
#define KW1 ((float)(d_e2/d_s))
#define KW2 ((float)(1.0 /d_s))

// ================= init: H0 = exp(log), marg0 = sum_j H0, r=c=1 ================
__global__ void k_init(const float* __restrict__ lg) {
    int t   = blockIdx.x*blockDim.x + threadIdx.x;   // 131072 threads
    int b   = t >> 12;
    int pix = (t & 4095) << 2;

    const __half2 one2 = __floats2half2_rn(1.f, 1.f);
    #pragma unroll
    for (int i = 0; i < NS; i++) {
        float a0 = 0.f, a1 = 0.f, a2 = 0.f, a3 = 0.f;
        #pragma unroll
        for (int j = 0; j < NS; j++) {
            size_t off = ((size_t)(b*NS*NS + i*NS + j))*HWP + pix;
            float4 v = *(const float4*)(lg + off);
            float e0 = expf(v.x), e1 = expf(v.y), e2 = expf(v.z), e3 = expf(v.w);
            __half2* hp = (__half2*)(g_H0 + off);
            hp[0] = __floats2half2_rn(e0, e1);
            hp[1] = __floats2half2_rn(e2, e3);
            a0 += e0; a1 += e1; a2 += e2; a3 += e3;
        }
        size_t moff = ((size_t)(b*NS + i))*HWP + pix;
        __half2* mp = (__half2*)(g_mA + moff);
        mp[0] = __floats2half2_rn(a0, a1);
        mp[1] = __floats2half2_rn(a2, a3);
        ((__half2*)(g_r + moff))[0] = one2;
        ((__half2*)(g_r + moff))[1] = one2;
        ((__half2*)(g_c + moff))[0] = one2;
        ((__half2*)(g_c + moff))[1] = one2;
    }
}

// ================= fused half step (2 px/thread, 512 threads) ===================
// MODE 0: smooth marg_in -> r /= (s+eps); marg_out_j = c_j * sum_i H0[i][j]*r_i
// MODE 1: smooth marg_in -> c /= (s+eps); marg_out_i = r_i * sum_j H0[i][j]*c_j
template<int MODE>
__global__ __launch_bounds__(512, 2) void k_half(int ping, int b0) {
    __shared__ __align__(16) __half sm_m[TH+4][NS][WW];  // marginal tile + halo (24 KB)
    __shared__ __align__(16) float  sm_t[TH  ][NS][WW];  // vertical conv result (32 KB)

    const __half* __restrict__ min_ = ping ? g_mB : g_mA;
    __half*       __restrict__ mout = ping ? g_mA : g_mB;
    __half*       upd = (MODE == 0) ? g_r : g_c;
    const __half* oth = (MODE == 0) ? g_c : g_r;

    const int b   = b0 + blockIdx.y;
    const int h0  = blockIdx.x * TH;
    const int tid = threadIdx.x;                // 512 threads

    // ---- stage 1: load marginal tile (rows h0-2 .. h0+TH+1, circular) ----------
    #pragma unroll
    for (int k = 0; k < 3; k++) {               // 1536 uint4 / 512 threads
        int idx = tid + k*512;
        int rr  = idx >> 7;
        int rem = idx & 127;
        int ch  = rem >> 4;
        int w8  = (rem & 15) << 3;
        int gh  = (h0 - 2 + rr) & (HH-1);
        *(uint4*)(&sm_m[rr][ch][w8]) =
            *(const uint4*)(min_ + ((size_t)(b*NS + ch))*HWP + gh*WW + w8);
    }
    __syncthreads();

    // ---- stage 2: vertical 5-tap, half2 granularity (4096 units / 512 thr) -----
    #pragma unroll
    for (int k = 0; k < 8; k++) {
        int e2 = tid + k*512;
        int r  = e2 >> 9;
        int ch = (e2 >> 6) & 7;
        int w2 = (e2 & 63) << 1;                // even w
        float2 a0 = __half22float2(*(const __half2*)(&sm_m[r  ][ch][w2]));
        float2 a1 = __half22float2(*(const __half2*)(&sm_m[r+1][ch][w2]));
        float2 a2 = __half22float2(*(const __half2*)(&sm_m[r+2][ch][w2]));
        float2 a3 = __half22float2(*(const __half2*)(&sm_m[r+3][ch][w2]));
        float2 a4 = __half22float2(*(const __half2*)(&sm_m[r+4][ch][w2]));
        float2 o;
        o.x = KW0*a0.x + KW1*a1.x + KW2*a2.x + KW1*a3.x + KW0*a4.x;
        o.y = KW0*a0.y + KW1*a1.y + KW2*a2.y + KW1*a3.y + KW0*a4.y;
        *(float2*)(&sm_t[r][ch][w2]) = o;
    }
    __syncthreads();

    // ---- stage 3: horizontal 5-tap, factor update, contraction (2 px/thread) ---
    const int row = tid >> 6;                   // 0..7
    const int w0  = (tid & 63) << 1;            // 0,2,..,126
    const int h   = h0 + row;
    const size_t pixoff = (size_t)h*WW + w0;
    const size_t hbase  = (size_t)b*NS*NS*HWP + pixoff;

    float un[NS][2];
    #pragma unroll
    for (int u = 0; u < NS; u++) {
        float tm2 = sm_t[row][u][(w0 + 126) & 127];
        float tm1 = sm_t[row][u][(w0 + 127) & 127];
        float t0  = sm_t[row][u][w0];
        float t1  = sm_t[row][u][w0 + 1];
        float tp2 = sm_t[row][u][(w0 + 2) & 127];
        float tp3 = sm_t[row][u][(w0 + 3) & 127];
        float s0 = KW0*tm2 + KW1*tm1 + KW2*t0 + KW1*t1 + KW0*tp2;
        float s1 = KW0*tm1 + KW1*t0  + KW2*t1 + KW1*tp2 + KW0*tp3;

        size_t off = ((size_t)(b*NS + u))*HWP + pixoff;
        float2 f = __half22float2(*(const __half2*)(upd + off));
        un[u][0] = __fdividef(f.x, s0 + EPSV);
        un[u][1] = __fdividef(f.y, s1 + EPSV);
        *(__half2*)(upd + off) = __floats2half2_rn(un[u][0], un[u][1]);
    }

    #pragma unroll
    for (int vh = 0; vh < 2; vh++) {
        float acc[4][2];
        #pragma unroll
        for (int v = 0; v < 4; v++) acc[v][0] = acc[v][1] = 0.f;

        #pragma unroll
        for (int u = 0; u < NS; u++) {
            #pragma unroll
            for (int v = 0; v < 4; v++) {
                int vv = vh*4 + v;
                int cc = (MODE == 0) ? (u*NS + vv) : (vv*NS + u);
                float2 f = __half22float2(*(const __half2*)(g_H0 + hbase + (size_t)cc*HWP));
                acc[v][0] += f.x * un[u][0];
                acc[v][1] += f.y * un[u][1];
            }
        }

        #pragma unroll
        for (int v = 0; v < 4; v++) {
            int vv = vh*4 + v;
            size_t off = ((size_t)(b*NS + vv))*HWP + pixoff;
            float2 o = __half22float2(*(const __half2*)(oth + off));
            *(__half2*)(mout + off) = __floats2half2_rn(acc[v][0]*o.x, acc[v][1]*o.y);
        }
    }
}

// ================= final: out = exp(log)*r_i*c_j + eps (fp32 path) =============
__global__ void k_final(const float* __restrict__ lg, float* __restrict__ out) {
    int t   = blockIdx.x*blockDim.x + threadIdx.x;
    int b   = t >> 12;
    int pix = (t & 4095) << 2;

    float cf[NS][4];
    #pragma unroll
    for (int j = 0; j < NS; j++) {
        uint2 cv = *(const uint2*)(g_c + ((size_t)(b*NS + j))*HWP + pix);
        float2 c01 = __half22float2(*(__half2*)&cv.x);
        float2 c23 = __half22float2(*(__half2*)&cv.y);
        cf[j][0] = c01.x; cf[j][1] = c01.y; cf[j][2] = c23.x; cf[j][3] = c23.y;
    }
    #pragma unroll
    for (int i = 0; i < NS; i++) {
        uint2 rw = *(const uint2*)(g_r + ((size_t)(b*NS + i))*HWP + pix);
        float2 r01 = __half22float2(*(__half2*)&rw.x);
        float2 r23 = __half22float2(*(__half2*)&rw.y);
        #pragma unroll
        for (int j = 0; j < NS; j++) {
            size_t off = ((size_t)(b*NS*NS + i*NS + j))*HWP + pix;
            float4 v = *(const float4*)(lg + off);
            float4 o;
            o.x = expf(v.x)*r01.x*cf[j][0] + EPSV;
            o.y = expf(v.y)*r01.y*cf[j][1] + EPSV;
            o.z = expf(v.z)*r23.x*cf[j][2] + EPSV;
            o.w = expf(v.w)*r23.y*cf[j][3] + EPSV;
            *(float4*)(out + off) = o;
        }
    }
}

// ================= launch =======================================================
extern "C" void kernel_launch(void* const* d_in, const int* in_sizes, int n_in,
                              void* d_out, int out_size) {
    (void)in_sizes; (void)n_in; (void)out_size;
    const float* lg  = (const float*)d_in[0];
    float*       out = (float*)d_out;

    k_init<<<512, 256>>>(lg);

    dim3 hg(HH/TH, BSPL);            // (16,16) = 256 blocks x 512 thr = one wave
    for (int pass = 0; pass < BB/BSPL; pass++) {
        int b0 = pass * BSPL;        // temporal blocking: slice stays in L2
        for (int it = 0; it < 20; it++) {
            k_half<0><<<hg, 512>>>(0, b0);   // row step: update r
            k_half<1><<<hg, 512>>>(1, b0);   // col step: update c
        }
    }

    k_final<<<512, 256>>>(lg, out);
}